// round 16
// baseline (speedup 1.0000x reference)
#include <cuda_runtime.h>
#include <cuda_fp16.h>
#include <cstdint>
#include <math.h>

#define Nn 100000
#define Ee 1600000
#define EPt (Ee + Nn)                 // 1,700,000 edges incl. self loops
#define OFF_EI (Nn * 32)              // 3,200,000
#define OFF_ALPHA (OFF_EI + 2 * EPt)  // 6,600,000
#define NB_SCAN ((Nn + 255) / 256)    // 391
#define W1N 136                       // 128 h cols + 4 als1 + 4 ald1
#define W2N 40                        // 32 h2f cols + als2 + ald2 + 6 pad

// ---------------- scratch (no allocations allowed) ----------------
__device__ __half2 g_hh[Nn * 64];      // layer1 features h = x@W1 (fp16)
__device__ __half2 g_h1h[Nn * 64];     // layer1 output h1 (fp16)
__device__ __half2 g_h2fh[Nn * 16];    // layer2 transformed features (fp16)
__device__ __align__(16) float g_als1[Nn * 4];
__device__ __align__(16) float g_ald1[Nn * 4];
__device__ float g_deg[Nn];
__device__ float g_ns2[Nn];            // per-node sum of s2 (written by agg1)
__device__ float g_s2[Ee];
__device__ float g_als2[Nn];
__device__ float g_ald2[Nn];
__device__ __align__(8) float2 g_adz[Nn];  // (ald2, z2) packed, written by agg2
__device__ float g_v1e[64];
__device__ float g_v2e[16];
__device__ __align__(16) float g_A1s[128 * 4];
__device__ __align__(16) float g_A1d[128 * 4];
__device__ __align__(16) float g_A2s[128];
__device__ __align__(16) float g_A2d[128];
__device__ __align__(16) __half g_W1aug[128 * W1N];
__device__ __align__(16) __half g_W2aug[128 * W2N];
// CSR structures: packed 16-byte record per slot: {half s1[4]; int src; float cs2}
__device__ int   g_off[Nn + 1];
__device__ int   g_cursor[Nn];
__device__ __align__(16) uint4 g_edge[EPt];
// decoupled-lookback scan tiles: bits[63:62] = status (0 invalid, 1 aggregate, 2 prefix)
__device__ unsigned long long g_tile[NB_SCAN];

__device__ __forceinline__ float elu_f(float v) { return v > 0.f ? v : expm1f(v); }
__device__ __forceinline__ float lrelu_f(float v) { return v > 0.f ? v : 0.2f * v; }

// ---- mma helpers ----
__device__ __forceinline__ unsigned int cvta_s(const void* p) {
    return (unsigned int)__cvta_generic_to_shared(p);
}
__device__ __forceinline__ void ldsm_x4(unsigned int& r0, unsigned int& r1,
                                        unsigned int& r2, unsigned int& r3,
                                        unsigned int addr) {
    asm volatile("ldmatrix.sync.aligned.m8n8.x4.shared.b16 {%0,%1,%2,%3}, [%4];"
                 : "=r"(r0), "=r"(r1), "=r"(r2), "=r"(r3) : "r"(addr));
}
__device__ __forceinline__ void ldsm_x4t(unsigned int& r0, unsigned int& r1,
                                         unsigned int& r2, unsigned int& r3,
                                         unsigned int addr) {
    asm volatile("ldmatrix.sync.aligned.m8n8.x4.trans.shared.b16 {%0,%1,%2,%3}, [%4];"
                 : "=r"(r0), "=r"(r1), "=r"(r2), "=r"(r3) : "r"(addr));
}
__device__ __forceinline__ void ldsm_x2t(unsigned int& r0, unsigned int& r1,
                                         unsigned int addr) {
    asm volatile("ldmatrix.sync.aligned.m8n8.x2.trans.shared.b16 {%0,%1}, [%2];"
                 : "=r"(r0), "=r"(r1) : "r"(addr));
}
__device__ __forceinline__ void mma_16816(float* c, unsigned int a0, unsigned int a1,
                                          unsigned int a2, unsigned int a3,
                                          unsigned int b0, unsigned int b1) {
    asm volatile(
        "mma.sync.aligned.m16n8k16.row.col.f32.f16.f16.f32 "
        "{%0,%1,%2,%3}, {%4,%5,%6,%7}, {%8,%9}, {%0,%1,%2,%3};"
        : "+f"(c[0]), "+f"(c[1]), "+f"(c[2]), "+f"(c[3])
        : "r"(a0), "r"(a1), "r"(a2), "r"(a3), "r"(b0), "r"(b1));
}

// ---------------- kernels ----------------

// small dot products only: v1e/v2e, A1s/A1d, A2s/A2d  (1 block)
__global__ void prep_small(const float* __restrict__ W1e, const float* __restrict__ a1e,
                           const float* __restrict__ W2e, const float* __restrict__ a2e,
                           const float* __restrict__ W1, const float* __restrict__ a1s,
                           const float* __restrict__ a1d, const float* __restrict__ W2,
                           const float* __restrict__ a2s, const float* __restrict__ a2d) {
    int t = threadIdx.x;  // 512 threads
    if (t < 64) {
        int ed = t >> 2;
        int h = t & 3;
        float s = 0.f;
        #pragma unroll
        for (int c = 0; c < 32; c++) {
            s += W1e[ed * 128 + h * 32 + c] * a1e[h * 32 + c];
        }
        g_v1e[t] = s;
    }
    if (t < 16) {
        float s = 0.f;
        #pragma unroll
        for (int c = 0; c < 32; c++) {
            s += W2e[t * 32 + c] * a2e[c];
        }
        g_v2e[t] = s;
    }
    {
        int k = t >> 2;
        int h = t & 3;
        float s = 0.f;
        float d = 0.f;
        #pragma unroll
        for (int c = 0; c < 32; c++) {
            float w = W1[k * 128 + h * 32 + c];
            s += w * a1s[h * 32 + c];
            d += w * a1d[h * 32 + c];
        }
        g_A1s[t] = s;
        g_A1d[t] = d;
    }
    if (t < 128) {
        float s = 0.f;
        float d = 0.f;
        #pragma unroll
        for (int c = 0; c < 32; c++) {
            float w = W2[t * 32 + c];
            s += w * a2s[c];
            d += w * a2d[c];
        }
        g_A2s[t] = s;
        g_A2d[t] = d;
    }
}

// gridded fill of the augmented fp16 weight matrices
__global__ void prep_aug(const float* __restrict__ W1, const float* __restrict__ W2) {
    int i = blockIdx.x * blockDim.x + threadIdx.x;
    if (i < 128 * W1N) {
        int k = i / W1N;
        int n = i - k * W1N;
        float v;
        if (n < 128) {
            v = W1[k * 128 + n];
        } else if (n < 132) {
            v = g_A1s[k * 4 + (n - 128)];
        } else {
            v = g_A1d[k * 4 + (n - 132)];
        }
        g_W1aug[i] = __float2half_rn(v);
    } else if (i < 128 * W1N + 128 * W2N) {
        int j = i - 128 * W1N;
        int k = j / W2N;
        int n = j - k * W2N;
        float v = 0.f;
        if (n < 32) {
            v = W2[k * 32 + n];
        } else if (n == 32) {
            v = g_A2s[k];
        } else if (n == 33) {
            v = g_A2d[k];
        }
        g_W2aug[j] = __float2half_rn(v);
    }
}

// degree count only
__global__ void deg_k(const int* __restrict__ ei) {
    int e = blockIdx.x * blockDim.x + threadIdx.x;
    if (e >= Ee) return;
    atomicAdd(&g_deg[ei[Ee + e]], 1.f);
}

// single-pass decoupled-lookback exclusive scan of deg -> g_off, g_cursor
__global__ void scan_lookback() {
    __shared__ int sh[256];
    __shared__ int s_prev;
    int b = blockIdx.x;
    int t = threadIdx.x;
    int n = b * 256 + t;
    int val = (n < Nn) ? (int)g_deg[n] : 0;
    sh[t] = val;
    __syncthreads();
    for (int off = 1; off < 256; off <<= 1) {
        int v = (t >= off) ? sh[t - off] : 0;
        __syncthreads();
        sh[t] += v;
        __syncthreads();
    }
    int total = sh[255];
    if (t == 0) {
        atomicExch(&g_tile[b], (1ull << 62) | (unsigned int)total);
        int prev = 0;
        for (int i = b - 1; i >= 0;) {
            unsigned long long v;
            do {
                v = atomicAdd(&g_tile[i], 0ull);
            } while ((v >> 62) == 0ull);
            prev += (int)(v & 0xffffffffull);
            if ((v >> 62) == 2ull) break;
            i--;
        }
        atomicExch(&g_tile[b], (2ull << 62) | (unsigned int)(prev + total));
        s_prev = prev;
    }
    __syncthreads();
    int off = s_prev + sh[t] - val;
    if (n < Nn) {
        g_off[n] = off;
        g_cursor[n] = off;
    }
    if (n == 0) g_off[Nn] = Ee;
}

// edge_index_sl (as float) — no dependencies, runs early overlapped
__global__ void ei_out(const int* __restrict__ ei, float* __restrict__ out) {
    int e = blockIdx.x * blockDim.x + threadIdx.x;
    if (e >= EPt) return;
    int s, d;
    if (e < Ee) {
        s = ei[e];
        d = ei[Ee + e];
    } else {
        s = e - Ee;
        d = s;
    }
    out[OFF_EI + e] = (float)s;
    out[OFF_EI + EPt + e] = (float)d;
}

// [h | als1 | ald1] = x @ W1aug via HMMA. 32 nodes per 256-thread block.
__global__ void gemm1_mma(const float* __restrict__ x) {
    __shared__ __align__(16) __half sW[128 * W1N];  // 34816 B
    __shared__ __align__(16) __half sX[32 * W1N];   //  8704 B (128 cols used)
    int tid = threadIdx.x;
    int n0 = blockIdx.x * 32;
    for (int i = tid; i < 128 * W1N / 8; i += 256) {
        ((uint4*)sW)[i] = ((const uint4*)g_W1aug)[i];
    }
    for (int i = tid; i < 2048; i += 256) {
        int r = i >> 6;
        int cp = i & 63;
        int node = n0 + r;
        float2 f = (node < Nn) ? *(const float2*)(x + (size_t)node * 128 + 2 * cp)
                               : make_float2(0.f, 0.f);
        *(__half2*)&sX[r * W1N + 2 * cp] = __floats2half2_rn(f.x, f.y);
    }
    __syncthreads();

    int w = tid >> 5;
    int lane = tid & 31;
    int mi = w & 1;
    int grp = w >> 1;
    const int baseArr[4] = {0, 5, 9, 13};
    const int cntArr[4] = {5, 4, 4, 4};
    int base = baseArr[grp];
    int cnt = cntArr[grp];

    float c[5][4];
    #pragma unroll
    for (int i = 0; i < 5; i++) {
        #pragma unroll
        for (int j = 0; j < 4; j++) {
            c[i][j] = 0.f;
        }
    }

    int arow = mi * 16 + (lane & 15);
    int acol = (lane >> 4) * 8;
    int brow0 = lane & 15;
    int bcol8 = (lane & 16) ? 8 : 0;

    for (int k0 = 0; k0 < 128; k0 += 16) {
        unsigned int a0, a1, a2, a3;
        ldsm_x4(a0, a1, a2, a3, cvta_s(&sX[arow * W1N + k0 + acol]));
        unsigned int b[5][2];
        #pragma unroll
        for (int tp = 0; tp < 2; tp++) {
            int ncol = (base + 2 * tp) * 8 + bcol8;
            ldsm_x4t(b[2 * tp][0], b[2 * tp][1], b[2 * tp + 1][0], b[2 * tp + 1][1],
                     cvta_s(&sW[(k0 + brow0) * W1N + ncol]));
        }
        if (cnt == 5) {
            int ncol = (base + 4) * 8;
            ldsm_x2t(b[4][0], b[4][1], cvta_s(&sW[(k0 + brow0) * W1N + ncol]));
        }
        #pragma unroll
        for (int t = 0; t < 5; t++) {
            if (t < cnt) {
                mma_16816(c[t], a0, a1, a2, a3, b[t][0], b[t][1]);
            }
        }
    }

    int r0 = n0 + mi * 16 + (lane >> 2);
    #pragma unroll
    for (int t = 0; t < 5; t++) {
        if (t >= cnt) continue;
        int ncol = (base + t) * 8 + 2 * (lane & 3);
        if (ncol < 128) {
            if (r0 < Nn) {
                g_hh[(size_t)r0 * 64 + (ncol >> 1)] = __floats2half2_rn(c[t][0], c[t][1]);
            }
            if (r0 + 8 < Nn) {
                g_hh[(size_t)(r0 + 8) * 64 + (ncol >> 1)] = __floats2half2_rn(c[t][2], c[t][3]);
            }
        } else if (ncol < 132) {
            int hh = ncol - 128;
            if (r0 < Nn) {
                g_als1[r0 * 4 + hh] = c[t][0];
                g_als1[r0 * 4 + hh + 1] = c[t][1];
            }
            if (r0 + 8 < Nn) {
                g_als1[(r0 + 8) * 4 + hh] = c[t][2];
                g_als1[(r0 + 8) * 4 + hh + 1] = c[t][3];
            }
        } else {
            int hh = ncol - 132;
            if (r0 < Nn) {
                g_ald1[r0 * 4 + hh] = c[t][0];
                g_ald1[r0 * 4 + hh + 1] = c[t][1];
            }
            if (r0 + 8 < Nn) {
                g_ald1[(r0 + 8) * 4 + hh] = c[t][2];
                g_ald1[(r0 + 8) * 4 + hh + 1] = c[t][3];
            }
        }
    }
}

// slim scatter: edge features -> s1 (fp16) / s2, packed CSR record. One atomic per edge.
// Independent of gemm1 — runs on the side stream overlapped with it.
__global__ void edge_scatter(const int* __restrict__ ei, const float* __restrict__ eattr) {
    int e = blockIdx.x * blockDim.x + threadIdx.x;
    if (e >= Ee) return;
    int src = ei[e];
    int dst = ei[Ee + e];
    int pos = atomicAdd(&g_cursor[dst], 1);
    float a[16];
    const float4* p = (const float4*)(eattr + (size_t)e * 16);
    #pragma unroll
    for (int q = 0; q < 4; q++) {
        float4 v = p[q];
        a[q * 4 + 0] = v.x;
        a[q * 4 + 1] = v.y;
        a[q * 4 + 2] = v.z;
        a[q * 4 + 3] = v.w;
    }
    float s0 = 0.f, s1 = 0.f, s2c = 0.f, s3 = 0.f, s2v = 0.f;
    #pragma unroll
    for (int ed = 0; ed < 16; ed++) {
        float av = a[ed];
        s0 += av * g_v1e[ed * 4 + 0];
        s1 += av * g_v1e[ed * 4 + 1];
        s2c += av * g_v1e[ed * 4 + 2];
        s3 += av * g_v1e[ed * 4 + 3];
        s2v += av * g_v2e[ed];
    }
    g_s2[e] = s2v;
    union { struct { __half2 sa; __half2 sb; int src; float cs2; } rec; uint4 u; } cv;
    cv.rec.sa = __floats2half2_rn(s0, s1);
    cv.rec.sb = __floats2half2_rn(s2c, s3);
    cv.rec.src = src;
    cv.rec.cs2 = s2v;
    g_edge[pos] = cv.u;
}

// warp-per-node layer1: logits+exp computed here; self-loop handled inline; writes ns2.
__global__ void agg1_csr(const float* __restrict__ b1) {
    int n = (blockIdx.x * blockDim.x + threadIdx.x) >> 5;
    if (n >= Nn) return;
    int lane = threadIdx.x & 31;
    int sub = lane >> 2;          // edge slot within 8-block
    int hq = lane & 3;            // head this lane evaluates logits for
    int l15 = lane & 15;
    int hl = l15 >> 2;            // head owning this lane's 8 channels
    int half_ = lane >> 4;
    int beg = g_off[n];
    int end = g_off[n + 1];

    float ald1n = g_ald1[n * 4 + hq];
    float als1n = g_als1[n * 4 + hq];

    float acc0 = 0.f, acc1 = 0.f, acc2 = 0.f, acc3 = 0.f;
    float acc4 = 0.f, acc5 = 0.f, acc6 = 0.f, acc7 = 0.f;
    float zl = 0.f, ss1 = 0.f, scs = 0.f;

    int idx = beg + sub;
    uint4 rec = make_uint4(0u, 0u, 0u, 0u);
    float als = 0.f;
    if (idx < end) {
        rec = g_edge[idx];
        als = g_als1[((const int*)&rec)[2] * 4 + hq];
    }
    for (int g = beg; g < end; g += 8) {
        int idxn = g + 8 + sub;
        uint4 recn = make_uint4(0u, 0u, 0u, 0u);
        if (idxn < end) {
            recn = g_edge[idxn];
        }
        float p = 0.f;
        int src = ((const int*)&rec)[2];
        if (g + sub < end) {
            float s1h = __half2float(((const __half*)&rec)[hq]);
            ss1 += s1h;
            if (hq == 0) {
                scs += ((const float*)&rec)[3];
            }
            p = __expf(lrelu_f(als + ald1n + s1h));
        }
        zl += p;
        int lim = end - g;
        #pragma unroll
        for (int t = 0; t < 8; t += 2) {
            if (t >= lim) break;
            int slot = t + half_;
            float pe = __shfl_sync(0xffffffffu, p, slot * 4 + hl);
            int se = __shfl_sync(0xffffffffu, src, slot * 4);
            uint4 v = *(const uint4*)((const char*)g_hh + (size_t)se * 256 + l15 * 16);
            float2 f0 = __half22float2(*(__half2*)&v.x);
            float2 f1 = __half22float2(*(__half2*)&v.y);
            float2 f2 = __half22float2(*(__half2*)&v.z);
            float2 f3 = __half22float2(*(__half2*)&v.w);
            acc0 += pe * f0.x;
            acc1 += pe * f0.y;
            acc2 += pe * f1.x;
            acc3 += pe * f1.y;
            acc4 += pe * f2.x;
            acc5 += pe * f2.y;
            acc6 += pe * f3.x;
            acc7 += pe * f3.y;
        }
        float alsn = 0.f;
        if (idxn < end) {
            alsn = g_als1[((const int*)&recn)[2] * 4 + hq];
        }
        rec = recn;
        als = alsn;
    }
    zl += __shfl_xor_sync(0xffffffffu, zl, 4);
    zl += __shfl_xor_sync(0xffffffffu, zl, 8);
    zl += __shfl_xor_sync(0xffffffffu, zl, 16);
    ss1 += __shfl_xor_sync(0xffffffffu, ss1, 4);
    ss1 += __shfl_xor_sync(0xffffffffu, ss1, 8);
    ss1 += __shfl_xor_sync(0xffffffffu, ss1, 16);
    scs += __shfl_xor_sync(0xffffffffu, scs, 4);
    scs += __shfl_xor_sync(0xffffffffu, scs, 8);
    scs += __shfl_xor_sync(0xffffffffu, scs, 16);

    float degf = (float)(end - beg);
    float invd = 1.f / fmaxf(degf, 1.f);
    float p_self = __expf(lrelu_f(als1n + ald1n + ss1 * invd));
    zl += p_self;

    acc0 += __shfl_xor_sync(0xffffffffu, acc0, 16);
    acc1 += __shfl_xor_sync(0xffffffffu, acc1, 16);
    acc2 += __shfl_xor_sync(0xffffffffu, acc2, 16);
    acc3 += __shfl_xor_sync(0xffffffffu, acc3, 16);
    acc4 += __shfl_xor_sync(0xffffffffu, acc4, 16);
    acc5 += __shfl_xor_sync(0xffffffffu, acc5, 16);
    acc6 += __shfl_xor_sync(0xffffffffu, acc6, 16);
    acc7 += __shfl_xor_sync(0xffffffffu, acc7, 16);

    {
        float pe = __shfl_sync(0xffffffffu, p_self, hl);
        uint4 v = *(const uint4*)((const char*)g_hh + (size_t)n * 256 + l15 * 16);
        float2 f0 = __half22float2(*(__half2*)&v.x);
        float2 f1 = __half22float2(*(__half2*)&v.y);
        float2 f2 = __half22float2(*(__half2*)&v.z);
        float2 f3 = __half22float2(*(__half2*)&v.w);
        acc0 += pe * f0.x;
        acc1 += pe * f0.y;
        acc2 += pe * f1.x;
        acc3 += pe * f1.y;
        acc4 += pe * f2.x;
        acc5 += pe * f2.y;
        acc6 += pe * f3.x;
        acc7 += pe * f3.y;
    }
    float inv = 1.f / __shfl_sync(0xffffffffu, zl, hl);

    if (lane == 0) {
        g_ns2[n] = scs;
    }
    if (lane < 16) {
        float4 bA = ((const float4*)b1)[l15 * 2];
        float4 bB = ((const float4*)b1)[l15 * 2 + 1];
        uint4 o;
        *(__half2*)&o.x = __floats2half2_rn(elu_f(acc0 * inv + bA.x), elu_f(acc1 * inv + bA.y));
        *(__half2*)&o.y = __floats2half2_rn(elu_f(acc2 * inv + bA.z), elu_f(acc3 * inv + bA.w));
        *(__half2*)&o.z = __floats2half2_rn(elu_f(acc4 * inv + bB.x), elu_f(acc5 * inv + bB.y));
        *(__half2*)&o.w = __floats2half2_rn(elu_f(acc6 * inv + bB.z), elu_f(acc7 * inv + bB.w));
        *(uint4*)((char*)g_h1h + (size_t)n * 256 + l15 * 16) = o;
    }
}

// [h2f | als2 | ald2] = h1 @ W2aug via HMMA. 64 nodes per 256-thread block.
__global__ void gemm2_mma() {
    __shared__ __align__(16) __half sW[128 * W2N];  // 10240 B
    __shared__ __align__(16) __half sX[64 * W1N];   // 17408 B (128 cols used)
    int tid = threadIdx.x;
    int n0 = blockIdx.x * 64;
    for (int i = tid; i < 128 * W2N / 8; i += 256) {
        ((uint4*)sW)[i] = ((const uint4*)g_W2aug)[i];
    }
    for (int i = tid; i < 1024; i += 256) {
        int r = i >> 4;
        int q = i & 15;
        int node = n0 + r;
        uint4 v = (node < Nn) ? ((const uint4*)(g_h1h + (size_t)node * 64))[q]
                              : make_uint4(0u, 0u, 0u, 0u);
        *(uint4*)&sX[r * W1N + q * 8] = v;
    }
    __syncthreads();

    int w = tid >> 5;
    int lane = tid & 31;
    int mi = w & 3;
    int grp = w >> 2;
    int base = grp ? 3 : 0;
    int cnt = grp ? 2 : 3;

    float c[3][4];
    #pragma unroll
    for (int i = 0; i < 3; i++) {
        #pragma unroll
        for (int j = 0; j < 4; j++) {
            c[i][j] = 0.f;
        }
    }

    int arow = mi * 16 + (lane & 15);
    int acol = (lane >> 4) * 8;
    int brow0 = lane & 15;
    int bcol8 = (lane & 16) ? 8 : 0;

    for (int k0 = 0; k0 < 128; k0 += 16) {
        unsigned int a0, a1, a2, a3;
        ldsm_x4(a0, a1, a2, a3, cvta_s(&sX[arow * W1N + k0 + acol]));
        unsigned int b[3][2];
        {
            int ncol = base * 8 + bcol8;
            ldsm_x4t(b[0][0], b[0][1], b[1][0], b[1][1],
                     cvta_s(&sW[(k0 + brow0) * W2N + ncol]));
        }
        if (cnt == 3) {
            int ncol = (base + 2) * 8;
            ldsm_x2t(b[2][0], b[2][1], cvta_s(&sW[(k0 + brow0) * W2N + ncol]));
        }
        #pragma unroll
        for (int t = 0; t < 3; t++) {
            if (t < cnt) {
                mma_16816(c[t], a0, a1, a2, a3, b[t][0], b[t][1]);
            }
        }
    }

    int r0 = n0 + mi * 16 + (lane >> 2);
    #pragma unroll
    for (int t = 0; t < 3; t++) {
        if (t >= cnt) continue;
        int ncol = (base + t) * 8 + 2 * (lane & 3);
        if (ncol < 32) {
            if (r0 < Nn) {
                g_h2fh[(size_t)r0 * 16 + (ncol >> 1)] = __floats2half2_rn(c[t][0], c[t][1]);
            }
            if (r0 + 8 < Nn) {
                g_h2fh[(size_t)(r0 + 8) * 16 + (ncol >> 1)] = __floats2half2_rn(c[t][2], c[t][3]);
            }
        } else if (ncol == 32) {
            if (r0 < Nn) {
                g_als2[r0] = c[t][0];
                g_ald2[r0] = c[t][1];
            }
            if (r0 + 8 < Nn) {
                g_als2[r0 + 8] = c[t][2];
                g_ald2[r0 + 8] = c[t][3];
            }
        }
    }
}

// warp-per-node layer2: packed edge record, pipelined; self-loop inline; writes (ald2,z2).
__global__ void agg2_csr(const float* __restrict__ b2, float* __restrict__ out) {
    int n = (blockIdx.x * blockDim.x + threadIdx.x) >> 5;
    if (n >= Nn) return;
    int lane = threadIdx.x & 31;
    int grp = lane >> 3;
    int chp = lane & 7;
    int beg = g_off[n];
    int end = g_off[n + 1];
    float ald2n = g_ald2[n];

    float a0 = 0.f;
    float a1 = 0.f;
    float a2 = 0.f;
    float a3 = 0.f;
    float zl = 0.f;

    int idx = beg + lane;
    int src = 0;
    float cs = 0.f;
    float als = 0.f;
    if (idx < end) {
        uint4 r = g_edge[idx];
        src = ((const int*)&r)[2];
        cs = ((const float*)&r)[3];
        als = g_als2[src];
    }
    for (int g = beg; g < end; g += 32) {
        int idxn = g + 32 + lane;
        int srcn = 0;
        float csn = 0.f;
        if (idxn < end) {
            uint4 r = g_edge[idxn];
            srcn = ((const int*)&r)[2];
            csn = ((const float*)&r)[3];
        }
        float p = (g + lane < end) ? __expf(lrelu_f(als + ald2n + cs)) : 0.f;
        zl += p;
        int lim = min(32, end - g);
        #pragma unroll 4
        for (int t = 0; t < 32; t += 4) {
            if (t >= lim) break;
            int slot = t + grp;
            float pe = __shfl_sync(0xffffffffu, p, slot);
            int se = __shfl_sync(0xffffffffu, src, slot);
            float2 v = *(const float2*)((const char*)g_h2fh + (size_t)se * 64 + chp * 8);
            float2 f0 = __half22float2(*(__half2*)&v.x);
            float2 f1 = __half22float2(*(__half2*)&v.y);
            a0 += pe * f0.x;
            a1 += pe * f0.y;
            a2 += pe * f1.x;
            a3 += pe * f1.y;
        }
        float alsn = 0.f;
        if (idxn < end) {
            alsn = g_als2[srcn];
        }
        src = srcn;
        cs = csn;
        als = alsn;
    }
    a0 += __shfl_xor_sync(0xffffffffu, a0, 8);
    a0 += __shfl_xor_sync(0xffffffffu, a0, 16);
    a1 += __shfl_xor_sync(0xffffffffu, a1, 8);
    a1 += __shfl_xor_sync(0xffffffffu, a1, 16);
    a2 += __shfl_xor_sync(0xffffffffu, a2, 8);
    a2 += __shfl_xor_sync(0xffffffffu, a2, 16);
    a3 += __shfl_xor_sync(0xffffffffu, a3, 8);
    a3 += __shfl_xor_sync(0xffffffffu, a3, 16);
    #pragma unroll
    for (int off = 16; off; off >>= 1) {
        zl += __shfl_xor_sync(0xffffffffu, zl, off);
    }
    float degf = (float)(end - beg);
    float invd = 1.f / fmaxf(degf, 1.f);
    float p_self = __expf(lrelu_f(g_als2[n] + ald2n + g_ns2[n] * invd));
    zl += p_self;
    {
        float2 v = *(const float2*)((const char*)g_h2fh + (size_t)n * 64 + chp * 8);
        float2 f0 = __half22float2(*(__half2*)&v.x);
        float2 f1 = __half22float2(*(__half2*)&v.y);
        a0 += p_self * f0.x;
        a1 += p_self * f0.y;
        a2 += p_self * f1.x;
        a3 += p_self * f1.y;
    }
    if (lane == 0) g_adz[n] = make_float2(ald2n, zl);
    if (lane < 8) {
        float inv = 1.f / zl;
        float4 bv = ((const float4*)b2)[chp];
        float4 o;
        o.x = elu_f(a0 * inv + bv.x);
        o.y = elu_f(a1 * inv + bv.y);
        o.z = elu_f(a2 * inv + bv.z);
        o.w = elu_f(a3 * inv + bv.w);
        *(float4*)(out + (size_t)n * 32 + chp * 4) = o;
    }
}

// alpha2 in original edge order (2 random gathers per edge: als2[s], adz[d])
__global__ void alpha_k(const int* __restrict__ ei, float* __restrict__ out) {
    int e = blockIdx.x * blockDim.x + threadIdx.x;
    if (e >= EPt) return;
    int s, d;
    float base;
    if (e < Ee) {
        s = ei[e];
        d = ei[Ee + e];
        base = g_s2[e];
    } else {
        s = e - Ee;
        d = s;
        base = g_ns2[d] / fmaxf(g_deg[d], 1.f);
    }
    float2 adz = g_adz[d];
    float v = lrelu_f(g_als2[s] + adz.x + base);
    out[OFF_ALPHA + e] = __expf(v) / adz.y;
}

extern "C" void kernel_launch(void* const* d_in, const int* in_sizes, int n_in,
                              void* d_out, int out_size) {
    const float* x    = (const float*)d_in[0];
    const int*   ei   = (const int*)  d_in[1];
    const float* eat  = (const float*)d_in[2];
    const float* W1   = (const float*)d_in[3];
    const float* W1e  = (const float*)d_in[4];
    const float* a1s  = (const float*)d_in[5];
    const float* a1d  = (const float*)d_in[6];
    const float* a1e  = (const float*)d_in[7];
    const float* b1   = (const float*)d_in[8];
    const float* W2   = (const float*)d_in[9];
    const float* W2e  = (const float*)d_in[10];
    const float* a2s  = (const float*)d_in[11];
    const float* a2d  = (const float*)d_in[12];
    const float* a2e  = (const float*)d_in[13];
    const float* b2   = (const float*)d_in[14];
    float* out = (float*)d_out;
    (void)in_sizes;
    (void)n_in;
    (void)out_size;

    void* p_deg;
    void* p_tile;
    cudaGetSymbolAddress(&p_deg, g_deg);
    cudaGetSymbolAddress(&p_tile, g_tile);

    cudaStream_t sB;
    cudaStreamCreateWithFlags(&sB, cudaStreamNonBlocking);
    cudaEvent_t evF, evP, evJ;
    cudaEventCreateWithFlags(&evF, cudaEventDisableTiming);
    cudaEventCreateWithFlags(&evP, cudaEventDisableTiming);
    cudaEventCreateWithFlags(&evJ, cudaEventDisableTiming);

    cudaEventRecord(evF, 0);
    cudaStreamWaitEvent(sB, evF, 0);

    // branch A (legacy stream): prep (small+aug) + layer1 GEMM
    prep_small<<<1, 512>>>(W1e, a1e, W2e, a2e, W1, a1s, a1d, W2, a2s, a2d);
    cudaEventRecord(evP, 0);  // v1e/v2e ready for edge_scatter
    prep_aug<<<(128 * W1N + 128 * W2N + 255) / 256, 256>>>(W1, W2);
    gemm1_mma<<<(Nn + 31) / 32, 256>>>(x);

    // branch B: memsets + ei_out + degree + scan + edge_scatter (overlaps gemm1)
    cudaMemsetAsync(p_deg, 0, (size_t)Nn * 4, sB);
    cudaMemsetAsync(p_tile, 0, (size_t)NB_SCAN * 8, sB);
    ei_out<<<(EPt + 255) / 256, 256, 0, sB>>>(ei, out);
    deg_k<<<(Ee + 255) / 256, 256, 0, sB>>>(ei);
    scan_lookback<<<NB_SCAN, 256, 0, sB>>>();
    cudaStreamWaitEvent(sB, evP, 0);
    edge_scatter<<<(Ee + 255) / 256, 256, 0, sB>>>(ei, eat);

    cudaEventRecord(evJ, sB);
    cudaStreamWaitEvent(0, evJ, 0);

    agg1_csr<<<(Nn + 7) / 8, 256>>>(b1);
    gemm2_mma<<<(Nn + 63) / 64, 256>>>();
    agg2_csr<<<(Nn + 7) / 8, 256>>>(b2, out);
    alpha_k<<<(EPt + 255) / 256, 256>>>(ei, out);

    cudaStreamDestroy(sB);
    cudaEventDestroy(evF);
    cudaEventDestroy(evP);
    cudaEventDestroy(evJ);
}